// round 1
// baseline (speedup 1.0000x reference)
#include <cuda_runtime.h>
#include <cstdint>
#include <cstddef>

#define NN 50000
#define NE 800000
#define DI 256
#define DO 256
#define NR 8

// Scratch: xt[r][n][o] = sum_i x[n][i] * W[r][i][o]   (409.6 MB)
__device__ float g_xt[(size_t)NR * NN * DO];

__device__ __forceinline__ uint32_t f2tf32(float f) {
    uint32_t u;
    asm("cvt.rna.tf32.f32 %0, %1;" : "=r"(u) : "f"(f));
    return u;
}

// ---------------------------------------------------------------------------
// GEMM: per relation r, xt[r] = x @ W[r].   TF32 mma.sync.m16n8k8.
// Block tile 128(M) x 128(N), K-step 32. 256 threads = 8 warps (4M x 2N),
// warp tile 32x64 = 2x8 mma tiles of 16x8.
// ---------------------------------------------------------------------------
__global__ __launch_bounds__(256, 2)
void rgcn_gemm(const float* __restrict__ x, const float* __restrict__ w) {
    const int r  = blockIdx.z;
    const int m0 = blockIdx.x * 128;
    const int n0 = blockIdx.y * 128;

    __shared__ uint32_t As[128][36];   // pitch 36 (mod32 = 4) -> conflict-free frag loads
    __shared__ uint32_t Bs[32][136];   // pitch 136 (mod32 = 8) -> conflict-free frag loads

    const int tid  = threadIdx.x;
    const int lane = tid & 31;
    const int wid  = tid >> 5;
    const int wm   = wid & 3;    // 0..3
    const int wn   = wid >> 2;   // 0..1
    const int g    = lane >> 2;  // groupID 0..7
    const int t    = lane & 3;   // threadInGroup 0..3

    float c[2][8][4];
#pragma unroll
    for (int mi = 0; mi < 2; mi++)
#pragma unroll
        for (int ni = 0; ni < 8; ni++)
#pragma unroll
            for (int q = 0; q < 4; q++) c[mi][ni][q] = 0.0f;

    const float* wr = w + (size_t)r * DI * DO;

    for (int kt = 0; kt < DI; kt += 32) {
        // --- load A tile: 128 rows x 32 cols = 1024 float4
#pragma unroll
        for (int s = 0; s < 4; s++) {
            int v   = tid + s * 256;
            int row = v >> 3;     // 0..127
            int c4  = v & 7;      // 0..7
            int gm  = m0 + row;
            float4 val = make_float4(0.f, 0.f, 0.f, 0.f);
            if (gm < NN) val = *(const float4*)(x + (size_t)gm * DI + kt + c4 * 4);
            uint4 tv;
            tv.x = f2tf32(val.x); tv.y = f2tf32(val.y);
            tv.z = f2tf32(val.z); tv.w = f2tf32(val.w);
            *(uint4*)&As[row][c4 * 4] = tv;
        }
        // --- load B tile: 32 rows(k) x 128 cols(o) = 1024 float4
#pragma unroll
        for (int s = 0; s < 4; s++) {
            int v   = tid + s * 256;
            int row = v >> 5;     // 0..31
            int c4  = v & 31;     // 0..31
            float4 val = *(const float4*)(wr + (size_t)(kt + row) * DO + n0 + c4 * 4);
            uint4 tv;
            tv.x = f2tf32(val.x); tv.y = f2tf32(val.y);
            tv.z = f2tf32(val.z); tv.w = f2tf32(val.w);
            *(uint4*)&Bs[row][c4 * 4] = tv;
        }
        __syncthreads();

#pragma unroll
        for (int kk = 0; kk < 4; kk++) {
            const int k8 = kk * 8;
            uint32_t a[2][4];
#pragma unroll
            for (int mi = 0; mi < 2; mi++) {
                int row = wm * 32 + mi * 16 + g;
                a[mi][0] = As[row][k8 + t];
                a[mi][1] = As[row + 8][k8 + t];
                a[mi][2] = As[row][k8 + t + 4];
                a[mi][3] = As[row + 8][k8 + t + 4];
            }
            uint32_t b[8][2];
#pragma unroll
            for (int ni = 0; ni < 8; ni++) {
                int col = wn * 64 + ni * 8 + g;
                b[ni][0] = Bs[k8 + t][col];
                b[ni][1] = Bs[k8 + t + 4][col];
            }
#pragma unroll
            for (int mi = 0; mi < 2; mi++)
#pragma unroll
                for (int ni = 0; ni < 8; ni++) {
                    asm volatile(
                        "mma.sync.aligned.m16n8k8.row.col.f32.tf32.tf32.f32 "
                        "{%0,%1,%2,%3}, {%4,%5,%6,%7}, {%8,%9}, {%0,%1,%2,%3};\n"
                        : "+f"(c[mi][ni][0]), "+f"(c[mi][ni][1]),
                          "+f"(c[mi][ni][2]), "+f"(c[mi][ni][3])
                        : "r"(a[mi][0]), "r"(a[mi][1]), "r"(a[mi][2]), "r"(a[mi][3]),
                          "r"(b[ni][0]), "r"(b[ni][1]));
                }
        }
        __syncthreads();
    }

    // --- store accumulators to g_xt[r]
    float* xtr = g_xt + (size_t)r * NN * DO;
#pragma unroll
    for (int mi = 0; mi < 2; mi++) {
#pragma unroll
        for (int ni = 0; ni < 8; ni++) {
            int row0 = m0 + wm * 32 + mi * 16 + g;
            int col  = n0 + wn * 64 + ni * 8 + t * 2;
            if (row0 < NN) {
                float2 v0 = make_float2(c[mi][ni][0], c[mi][ni][1]);
                *(float2*)(xtr + (size_t)row0 * DO + col) = v0;
            }
            int row1 = row0 + 8;
            if (row1 < NN) {
                float2 v1 = make_float2(c[mi][ni][2], c[mi][ni][3]);
                *(float2*)(xtr + (size_t)row1 * DO + col) = v1;
            }
        }
    }
}

// ---------------------------------------------------------------------------
// Scatter: one warp per edge. Gather xt[edge_type, col] (256 f32 = 8 f32/lane)
// and red.global.add.v4.f32 into out[row].
// ---------------------------------------------------------------------------
__global__ __launch_bounds__(256)
void rgcn_scatter(const int* __restrict__ edge_index,
                  const int* __restrict__ edge_type,
                  float* __restrict__ out) {
    const int wid_in_blk = threadIdx.x >> 5;
    const int lane = threadIdx.x & 31;
    const int e = blockIdx.x * 8 + wid_in_blk;
    if (e >= NE) return;

    const int row = edge_index[e];
    const int col = edge_index[NE + e];
    const int r   = edge_type[e];

    const float4* src = (const float4*)(g_xt + ((size_t)r * NN + (size_t)col) * DO);
    float* dst = out + (size_t)row * DO;

    float4 v0 = src[lane];
    float4 v1 = src[lane + 32];

    asm volatile("red.global.add.v4.f32 [%0], {%1,%2,%3,%4};"
                 :: "l"(dst + lane * 4), "f"(v0.x), "f"(v0.y), "f"(v0.z), "f"(v0.w)
                 : "memory");
    asm volatile("red.global.add.v4.f32 [%0], {%1,%2,%3,%4};"
                 :: "l"(dst + 128 + lane * 4), "f"(v1.x), "f"(v1.y), "f"(v1.z), "f"(v1.w)
                 : "memory");
}

// ---------------------------------------------------------------------------
// Init + epilogue
// ---------------------------------------------------------------------------
__global__ void rgcn_zero(float4* __restrict__ out) {
    size_t i = (size_t)blockIdx.x * blockDim.x + threadIdx.x;
    if (i < (size_t)NN * DO / 4) out[i] = make_float4(0.f, 0.f, 0.f, 0.f);
}

__global__ void rgcn_epilogue(float4* __restrict__ out, const float4* __restrict__ bias) {
    size_t i = (size_t)blockIdx.x * blockDim.x + threadIdx.x;
    if (i >= (size_t)NN * DO / 4) return;
    int c4 = (int)(i & (DO / 4 - 1));
    float4 b = bias[c4];
    float4 v = out[i];
    v.x = fmaxf(v.x + b.x, 0.f);
    v.y = fmaxf(v.y + b.y, 0.f);
    v.z = fmaxf(v.z + b.z, 0.f);
    v.w = fmaxf(v.w + b.w, 0.f);
    out[i] = v;
}

extern "C" void kernel_launch(void* const* d_in, const int* in_sizes, int n_in,
                              void* d_out, int out_size) {
    const float* x          = (const float*)d_in[0];
    const int*   edge_index = (const int*)d_in[1];
    const int*   edge_type  = (const int*)d_in[2];
    const float* weight     = (const float*)d_in[3];
    const float* bias       = (const float*)d_in[4];
    float* out = (float*)d_out;

    const int vec = NN * DO / 4;                 // 3.2M float4
    rgcn_zero<<<(vec + 255) / 256, 256>>>((float4*)out);

    dim3 gg((NN + 127) / 128, DO / 128, NR);     // 391 x 2 x 8
    rgcn_gemm<<<gg, 256>>>(x, weight);

    rgcn_scatter<<<NE / 8, 256>>>(edge_index, edge_type, out);

    rgcn_epilogue<<<(vec + 255) / 256, 256>>>((float4*)out, (const float4*)bias);
}

// round 3
// speedup vs baseline: 1.0226x; 1.0226x over previous
#include <cuda_runtime.h>
#include <cuda_fp16.h>
#include <cstdint>
#include <cstddef>

#define NN 50000
#define NE 800000
#define DI 256
#define DO 256
#define NR 8

// fp16 scratch: xt[r][n][o]  (204.8 MB)
__device__ __half g_xt[(size_t)NR * NN * DO];
// tf32-pre-rounded copies of x and W
__device__ float g_xr[(size_t)NN * DI];      // 51.2 MB
__device__ float g_wr[(size_t)NR * DI * DO]; // 2 MB

__device__ __forceinline__ float f2tf32(float f) {
    uint32_t u;
    asm("cvt.rna.tf32.f32 %0, %1;" : "=r"(u) : "f"(f));
    return __uint_as_float(u);
}

__device__ __forceinline__ void cp_async16(uint32_t saddr, const void* gaddr) {
    asm volatile("cp.async.cg.shared.global [%0], [%1], 16;" :: "r"(saddr), "l"(gaddr));
}
__device__ __forceinline__ void cp_async16_pred(uint32_t saddr, const void* gaddr, int sz) {
    asm volatile("cp.async.cg.shared.global [%0], [%1], 16, %2;"
                 :: "r"(saddr), "l"(gaddr), "r"(sz));
}
__device__ __forceinline__ uint32_t smem_u32(const void* p) {
    uint32_t a;
    asm("{ .reg .u64 t; cvta.to.shared.u64 t, %1; cvt.u32.u64 %0, t; }" : "=r"(a) : "l"(p));
    return a;
}

// ---------------------------------------------------------------------------
// Pre-round an fp32 array to tf32 (rna), elementwise, float4-vectorized.
// ---------------------------------------------------------------------------
__global__ void rgcn_round(const float4* __restrict__ src, float4* __restrict__ dst, int n4) {
    int i = blockIdx.x * blockDim.x + threadIdx.x;
    if (i >= n4) return;
    float4 v = src[i];
    v.x = f2tf32(v.x); v.y = f2tf32(v.y); v.z = f2tf32(v.z); v.w = f2tf32(v.w);
    dst[i] = v;
}

// ---------------------------------------------------------------------------
// GEMM: per relation r, xt[r] = x @ W[r] in fp16 out.
// tf32 mma.sync m16n8k8, 128x128 tile, BK=32, 3-stage cp.async pipeline.
// 256 threads = 8 warps (4M x 2N), warp tile 32x64.
// ---------------------------------------------------------------------------
#define BK 32
#define NCH (DI / BK)                 // 8
#define A_PITCH 36
#define B_PITCH 136
#define A_WORDS (128 * A_PITCH)       // floats per A stage
#define B_WORDS (BK * B_PITCH)
#define STAGE_WORDS (A_WORDS + B_WORDS)
#define SMEM_DYN (3 * STAGE_WORDS * 4)

__global__ __launch_bounds__(256, 2)
void rgcn_gemm(const float* __restrict__ x, const float* __restrict__ w,
               __half* __restrict__ xt) {
    extern __shared__ float smem[];

    const int r  = blockIdx.z;
    const int m0 = blockIdx.x * 128;
    const int n0 = blockIdx.y * 128;

    const int tid  = threadIdx.x;
    const int lane = tid & 31;
    const int wid  = tid >> 5;
    const int wm   = wid & 3;
    const int wn   = wid >> 2;
    const int g    = lane >> 2;
    const int t    = lane & 3;

    const uint32_t sbase = smem_u32(smem);
    const float* wr = w + (size_t)r * DI * DO;

    float c[2][8][4];
#pragma unroll
    for (int mi = 0; mi < 2; mi++)
#pragma unroll
        for (int ni = 0; ni < 8; ni++)
#pragma unroll
            for (int q = 0; q < 4; q++) c[mi][ni][q] = 0.0f;

    auto load_chunk = [&](int ci, int stage) {
        const int kt = ci * BK;
        const uint32_t sA = sbase + stage * STAGE_WORDS * 4;
        const uint32_t sB = sA + A_WORDS * 4;
#pragma unroll
        for (int u = 0; u < 4; u++) {
            int v = tid + u * 256;            // 1024 float4: A 128 rows x 8 f4
            int row = v >> 3, c4 = v & 7;
            int gm = m0 + row;
            uint32_t sa = sA + (row * A_PITCH + c4 * 4) * 4;
            cp_async16_pred(sa, x + (size_t)gm * DI + kt + c4 * 4, (gm < NN) ? 16 : 0);
        }
#pragma unroll
        for (int u = 0; u < 4; u++) {
            int v = tid + u * 256;            // 1024 float4: B 32 rows x 32 f4
            int row = v >> 5, c4 = v & 31;
            uint32_t sb = sB + (row * B_PITCH + c4 * 4) * 4;
            cp_async16(sb, wr + (size_t)(kt + row) * DO + n0 + c4 * 4);
        }
        asm volatile("cp.async.commit_group;" ::: "memory");
    };

    load_chunk(0, 0);
    load_chunk(1, 1);
    load_chunk(2, 2);

#pragma unroll
    for (int i = 0; i < NCH; i++) {
        if (i + 2 < NCH)      asm volatile("cp.async.wait_group 2;" ::: "memory");
        else if (i + 1 < NCH) asm volatile("cp.async.wait_group 1;" ::: "memory");
        else                  asm volatile("cp.async.wait_group 0;" ::: "memory");
        __syncthreads();

        const float* As = smem + (i % 3) * STAGE_WORDS;
        const float* Bs = As + A_WORDS;

#pragma unroll
        for (int kk = 0; kk < 4; kk++) {
            const int k8 = kk * 8;
            uint32_t a[2][4];
#pragma unroll
            for (int mi = 0; mi < 2; mi++) {
                int row = wm * 32 + mi * 16 + g;
                a[mi][0] = __float_as_uint(As[row * A_PITCH + k8 + t]);
                a[mi][1] = __float_as_uint(As[(row + 8) * A_PITCH + k8 + t]);
                a[mi][2] = __float_as_uint(As[row * A_PITCH + k8 + t + 4]);
                a[mi][3] = __float_as_uint(As[(row + 8) * A_PITCH + k8 + t + 4]);
            }
            uint32_t b[8][2];
#pragma unroll
            for (int ni = 0; ni < 8; ni++) {
                int col = wn * 64 + ni * 8 + g;
                b[ni][0] = __float_as_uint(Bs[(k8 + t) * B_PITCH + col]);
                b[ni][1] = __float_as_uint(Bs[(k8 + t + 4) * B_PITCH + col]);
            }
#pragma unroll
            for (int mi = 0; mi < 2; mi++)
#pragma unroll
                for (int ni = 0; ni < 8; ni++) {
                    asm volatile(
                        "mma.sync.aligned.m16n8k8.row.col.f32.tf32.tf32.f32 "
                        "{%0,%1,%2,%3}, {%4,%5,%6,%7}, {%8,%9}, {%0,%1,%2,%3};\n"
                        : "+f"(c[mi][ni][0]), "+f"(c[mi][ni][1]),
                          "+f"(c[mi][ni][2]), "+f"(c[mi][ni][3])
                        : "r"(a[mi][0]), "r"(a[mi][1]), "r"(a[mi][2]), "r"(a[mi][3]),
                          "r"(b[ni][0]), "r"(b[ni][1]));
                }
        }
        __syncthreads();
        if (i + 3 < NCH) load_chunk(i + 3, i % 3);
    }

    // store accumulators to fp16 xt[r]
    __half* xtr = xt + (size_t)r * NN * DO;
#pragma unroll
    for (int mi = 0; mi < 2; mi++) {
#pragma unroll
        for (int ni = 0; ni < 8; ni++) {
            int row0 = m0 + wm * 32 + mi * 16 + g;
            int col  = n0 + wn * 64 + ni * 8 + t * 2;
            if (row0 < NN)
                *(half2*)(xtr + (size_t)row0 * DO + col) =
                    __float22half2_rn(make_float2(c[mi][ni][0], c[mi][ni][1]));
            int row1 = row0 + 8;
            if (row1 < NN)
                *(half2*)(xtr + (size_t)row1 * DO + col) =
                    __float22half2_rn(make_float2(c[mi][ni][2], c[mi][ni][3]));
        }
    }
}

// ---------------------------------------------------------------------------
// Scatter: one warp per edge. 1 LDG.128 per lane (8 halves = 8 consecutive
// cols), convert, 2x red.global.add.v4.f32 into out[row].
// ---------------------------------------------------------------------------
__global__ __launch_bounds__(256)
void rgcn_scatter(const int* __restrict__ edge_index,
                  const int* __restrict__ edge_type,
                  const __half* __restrict__ xt,
                  float* __restrict__ out) {
    const int wib  = threadIdx.x >> 5;
    const int lane = threadIdx.x & 31;
    const int e = blockIdx.x * 8 + wib;
    if (e >= NE) return;

    const int row = edge_index[e];
    const int col = edge_index[NE + e];
    const int r   = edge_type[e];

    const uint4* src = (const uint4*)(xt + ((size_t)r * NN + (size_t)col) * DO);
    uint4 v = __ldg(src + lane);

    float2 f0 = __half22float2(*(const half2*)&v.x);
    float2 f1 = __half22float2(*(const half2*)&v.y);
    float2 f2 = __half22float2(*(const half2*)&v.z);
    float2 f3 = __half22float2(*(const half2*)&v.w);

    float* dst = out + (size_t)row * DO + lane * 8;
    asm volatile("red.global.add.v4.f32 [%0], {%1,%2,%3,%4};"
                 :: "l"(dst), "f"(f0.x), "f"(f0.y), "f"(f1.x), "f"(f1.y) : "memory");
    asm volatile("red.global.add.v4.f32 [%0], {%1,%2,%3,%4};"
                 :: "l"(dst + 4), "f"(f2.x), "f"(f2.y), "f"(f3.x), "f"(f3.y) : "memory");
}

// ---------------------------------------------------------------------------
// Init + epilogue
// ---------------------------------------------------------------------------
__global__ void rgcn_zero(float4* __restrict__ out) {
    size_t i = (size_t)blockIdx.x * blockDim.x + threadIdx.x;
    if (i < (size_t)NN * DO / 4) out[i] = make_float4(0.f, 0.f, 0.f, 0.f);
}

__global__ void rgcn_epilogue(float4* __restrict__ out, const float4* __restrict__ bias) {
    size_t i = (size_t)blockIdx.x * blockDim.x + threadIdx.x;
    if (i >= (size_t)NN * DO / 4) return;
    int c4 = (int)(i & (DO / 4 - 1));
    float4 b = bias[c4];
    float4 v = out[i];
    v.x = fmaxf(v.x + b.x, 0.f);
    v.y = fmaxf(v.y + b.y, 0.f);
    v.z = fmaxf(v.z + b.z, 0.f);
    v.w = fmaxf(v.w + b.w, 0.f);
    out[i] = v;
}

extern "C" void kernel_launch(void* const* d_in, const int* in_sizes, int n_in,
                              void* d_out, int out_size) {
    const float* x          = (const float*)d_in[0];
    const int*   edge_index = (const int*)d_in[1];
    const int*   edge_type  = (const int*)d_in[2];
    const float* weight     = (const float*)d_in[3];
    const float* bias       = (const float*)d_in[4];
    float* out = (float*)d_out;

    float *xr, *wr;
    __half* xt;
    cudaGetSymbolAddress((void**)&xr, g_xr);
    cudaGetSymbolAddress((void**)&wr, g_wr);
    cudaGetSymbolAddress((void**)&xt, g_xt);

    cudaFuncSetAttribute(rgcn_gemm, cudaFuncAttributeMaxDynamicSharedMemorySize, SMEM_DYN);

    const int xn4 = NN * DI / 4;
    const int wn4 = NR * DI * DO / 4;
    rgcn_round<<<(xn4 + 255) / 256, 256>>>((const float4*)x, (float4*)xr, xn4);
    rgcn_round<<<(wn4 + 255) / 256, 256>>>((const float4*)weight, (float4*)wr, wn4);

    const int vec = NN * DO / 4;
    rgcn_zero<<<(vec + 255) / 256, 256>>>((float4*)out);

    dim3 gg((NN + 127) / 128, DO / 128, NR);     // 391 x 2 x 8
    rgcn_gemm<<<gg, 256, SMEM_DYN>>>(xr, wr, xt);

    rgcn_scatter<<<NE / 8, 256>>>(edge_index, edge_type, xt, out);

    rgcn_epilogue<<<(vec + 255) / 256, 256>>>((float4*)out, (const float4*)bias);
}

// round 4
// speedup vs baseline: 1.1833x; 1.1572x over previous
#include <cuda_runtime.h>
#include <cuda_fp16.h>
#include <cstdint>
#include <cstddef>

#define NN 50000
#define NE 800000
#define DI 256
#define DO 256
#define NR 8

// fp16 scratch: xt[r][n][o]  (204.8 MB)
__device__ __half g_xt[(size_t)NR * NN * DO];
// tf32-pre-rounded copies of x and W
__device__ float g_xr[(size_t)NN * DI];
__device__ float g_wr[(size_t)NR * DI * DO];
// CSR-by-destination scaffolding
__device__ int g_cnt[NN];
__device__ int g_offs[NN + 1];
__device__ int g_curs[NN];
__device__ uint32_t g_perm[NE];     // packed payload: col | (rel<<16)

__device__ __forceinline__ float f2tf32(float f) {
    uint32_t u;
    asm("cvt.rna.tf32.f32 %0, %1;" : "=r"(u) : "f"(f));
    return __uint_as_float(u);
}
__device__ __forceinline__ void cp_async16(uint32_t saddr, const void* gaddr) {
    asm volatile("cp.async.cg.shared.global [%0], [%1], 16;" :: "r"(saddr), "l"(gaddr));
}
__device__ __forceinline__ void cp_async16_pred(uint32_t saddr, const void* gaddr, int sz) {
    asm volatile("cp.async.cg.shared.global [%0], [%1], 16, %2;"
                 :: "r"(saddr), "l"(gaddr), "r"(sz));
}
__device__ __forceinline__ uint32_t smem_u32(const void* p) {
    uint32_t a;
    asm("{ .reg .u64 t; cvta.to.shared.u64 t, %1; cvt.u32.u64 %0, t; }" : "=r"(a) : "l"(p));
    return a;
}

// ---------------------------------------------------------------------------
// tf32 pre-round (rna), float4-vectorized
// ---------------------------------------------------------------------------
__global__ void rgcn_round(const float4* __restrict__ src, float4* __restrict__ dst, int n4) {
    int i = blockIdx.x * blockDim.x + threadIdx.x;
    if (i >= n4) return;
    float4 v = src[i];
    v.x = f2tf32(v.x); v.y = f2tf32(v.y); v.z = f2tf32(v.z); v.w = f2tf32(v.w);
    dst[i] = v;
}

// ---------------------------------------------------------------------------
// CSR build: zero counts -> count -> scan (1 block) -> fill perm
// ---------------------------------------------------------------------------
__global__ void rgcn_zero_cnt(int* __restrict__ cnt) {
    int i = blockIdx.x * blockDim.x + threadIdx.x;
    if (i < NN) cnt[i] = 0;
}
__global__ void rgcn_count(const int* __restrict__ edge_index, int* __restrict__ cnt) {
    int e = blockIdx.x * blockDim.x + threadIdx.x;
    if (e < NE) atomicAdd(&cnt[edge_index[e]], 1);
}
__global__ __launch_bounds__(1024)
void rgcn_scan(const int* __restrict__ cnt, int* __restrict__ offs, int* __restrict__ curs) {
    __shared__ int ssum[1024];
    const int t = threadIdx.x;
    const int PER = (NN + 1023) / 1024;      // 49
    const int base = t * PER;
    int s = 0;
    for (int k = 0; k < PER; k++) {
        int i = base + k;
        if (i < NN) s += cnt[i];
    }
    ssum[t] = s;
    __syncthreads();
    for (int d = 1; d < 1024; d <<= 1) {
        int v = (t >= d) ? ssum[t - d] : 0;
        __syncthreads();
        ssum[t] += v;
        __syncthreads();
    }
    int run = ssum[t] - s;                   // exclusive prefix
    for (int k = 0; k < PER; k++) {
        int i = base + k;
        if (i < NN) {
            offs[i] = run;
            curs[i] = run;
            run += cnt[i];
        }
    }
    if (t == 1023) offs[NN] = ssum[1023];
}
__global__ void rgcn_fill(const int* __restrict__ edge_index,
                          const int* __restrict__ edge_type,
                          int* __restrict__ curs, uint32_t* __restrict__ perm) {
    int e = blockIdx.x * blockDim.x + threadIdx.x;
    if (e >= NE) return;
    int row = edge_index[e];
    int col = edge_index[NE + e];
    int r   = edge_type[e];
    int pos = atomicAdd(&curs[row], 1);
    perm[pos] = (uint32_t)col | ((uint32_t)r << 16);
}

// ---------------------------------------------------------------------------
// GEMM: xt[r] = x @ W[r], fp16 out. tf32 mma m16n8k8.
// CTA: 128 threads (4 warps, 2x2), tile 128x128, warp tile 64x64.
// BK=32, 2-stage cp.async double buffer, 2 CTAs/SM.
// ---------------------------------------------------------------------------
#define BK 32
#define NCH (DI / BK)                 // 8
#define A_PITCH 36
#define B_PITCH 136
#define A_WORDS (128 * A_PITCH)
#define B_WORDS (BK * B_PITCH)
#define STAGE_WORDS (A_WORDS + B_WORDS)
#define SMEM_DYN (2 * STAGE_WORDS * 4)

__global__ __launch_bounds__(128, 2)
void rgcn_gemm(const float* __restrict__ x, const float* __restrict__ w,
               __half* __restrict__ xt) {
    extern __shared__ float smem[];

    const int r  = blockIdx.z;
    const int m0 = blockIdx.x * 128;
    const int n0 = blockIdx.y * 128;

    const int tid  = threadIdx.x;
    const int lane = tid & 31;
    const int wid  = tid >> 5;
    const int wm   = wid & 1;     // m half (64)
    const int wn   = wid >> 1;    // n half (64)
    const int g    = lane >> 2;
    const int t    = lane & 3;

    const uint32_t sbase = smem_u32(smem);
    const float* wr = w + (size_t)r * DI * DO;

    float c[4][8][4];
#pragma unroll
    for (int mi = 0; mi < 4; mi++)
#pragma unroll
        for (int ni = 0; ni < 8; ni++)
#pragma unroll
            for (int q = 0; q < 4; q++) c[mi][ni][q] = 0.0f;

    auto load_chunk = [&](int ci, int stage) {
        const int kt = ci * BK;
        const uint32_t sA = sbase + stage * STAGE_WORDS * 4;
        const uint32_t sB = sA + A_WORDS * 4;
#pragma unroll
        for (int u = 0; u < 8; u++) {
            int v = tid + u * 128;            // A: 1024 f4 = 128 rows x 8
            int row = v >> 3, c4 = v & 7;
            int gm = m0 + row;
            uint32_t sa = sA + (row * A_PITCH + c4 * 4) * 4;
            cp_async16_pred(sa, x + (size_t)gm * DI + kt + c4 * 4, (gm < NN) ? 16 : 0);
        }
#pragma unroll
        for (int u = 0; u < 8; u++) {
            int v = tid + u * 128;            // B: 1024 f4 = 32 rows x 32
            int row = v >> 5, c4 = v & 31;
            uint32_t sb = sB + (row * B_PITCH + c4 * 4) * 4;
            cp_async16(sb, wr + (size_t)(kt + row) * DO + n0 + c4 * 4);
        }
        asm volatile("cp.async.commit_group;" ::: "memory");
    };

    load_chunk(0, 0);

#pragma unroll
    for (int i = 0; i < NCH; i++) {
        if (i + 1 < NCH) {
            load_chunk(i + 1, (i + 1) & 1);
            asm volatile("cp.async.wait_group 1;" ::: "memory");
        } else {
            asm volatile("cp.async.wait_group 0;" ::: "memory");
        }
        __syncthreads();

        const float* As = smem + (i & 1) * STAGE_WORDS;
        const float* Bs = As + A_WORDS;

#pragma unroll
        for (int kk = 0; kk < 4; kk++) {
            const int k8 = kk * 8;
            uint32_t a[4][4];
#pragma unroll
            for (int mi = 0; mi < 4; mi++) {
                int row = wm * 64 + mi * 16 + g;
                a[mi][0] = __float_as_uint(As[row * A_PITCH + k8 + t]);
                a[mi][1] = __float_as_uint(As[(row + 8) * A_PITCH + k8 + t]);
                a[mi][2] = __float_as_uint(As[row * A_PITCH + k8 + t + 4]);
                a[mi][3] = __float_as_uint(As[(row + 8) * A_PITCH + k8 + t + 4]);
            }
#pragma unroll
            for (int ni = 0; ni < 8; ni++) {
                int col = wn * 64 + ni * 8 + g;
                uint32_t b0 = __float_as_uint(Bs[(k8 + t) * B_PITCH + col]);
                uint32_t b1 = __float_as_uint(Bs[(k8 + t + 4) * B_PITCH + col]);
#pragma unroll
                for (int mi = 0; mi < 4; mi++) {
                    asm volatile(
                        "mma.sync.aligned.m16n8k8.row.col.f32.tf32.tf32.f32 "
                        "{%0,%1,%2,%3}, {%4,%5,%6,%7}, {%8,%9}, {%0,%1,%2,%3};\n"
                        : "+f"(c[mi][ni][0]), "+f"(c[mi][ni][1]),
                          "+f"(c[mi][ni][2]), "+f"(c[mi][ni][3])
                        : "r"(a[mi][0]), "r"(a[mi][1]), "r"(a[mi][2]), "r"(a[mi][3]),
                          "r"(b0), "r"(b1));
                }
            }
        }
        __syncthreads();
    }

    __half* xtr = xt + (size_t)r * NN * DO;
#pragma unroll
    for (int mi = 0; mi < 4; mi++) {
#pragma unroll
        for (int ni = 0; ni < 8; ni++) {
            int row0 = m0 + wm * 64 + mi * 16 + g;
            int col  = n0 + wn * 64 + ni * 8 + t * 2;
            if (row0 < NN)
                *(half2*)(xtr + (size_t)row0 * DO + col) =
                    __float22half2_rn(make_float2(c[mi][ni][0], c[mi][ni][1]));
            int row1 = row0 + 8;
            if (row1 < NN)
                *(half2*)(xtr + (size_t)row1 * DO + col) =
                    __float22half2_rn(make_float2(c[mi][ni][2], c[mi][ni][3]));
        }
    }
}

// ---------------------------------------------------------------------------
// Aggregate: one warp per destination node. Register accumulation, no atomics.
// Fused bias + relu. Each lane owns 8 consecutive output floats.
// ---------------------------------------------------------------------------
__global__ __launch_bounds__(256)
void rgcn_aggregate(const __half* __restrict__ xt,
                    const float* __restrict__ bias,
                    const int* __restrict__ offs,
                    const uint32_t* __restrict__ perm,
                    float* __restrict__ out) {
    const int n = blockIdx.x * 8 + (threadIdx.x >> 5);
    if (n >= NN) return;
    const int lane = threadIdx.x & 31;

    const int s = offs[n];
    const int e = offs[n + 1];

    float acc[8];
#pragma unroll
    for (int k = 0; k < 8; k++) acc[k] = 0.0f;

    int j = s;
    for (; j + 1 < e; j += 2) {
        uint32_t p0 = perm[j], p1 = perm[j + 1];
        const uint4* s0 = (const uint4*)(xt +
            (((size_t)(p0 >> 16)) * NN + (size_t)(p0 & 0xFFFFu)) * DO) + lane;
        const uint4* s1 = (const uint4*)(xt +
            (((size_t)(p1 >> 16)) * NN + (size_t)(p1 & 0xFFFFu)) * DO) + lane;
        uint4 v0 = __ldg(s0);
        uint4 v1 = __ldg(s1);
        float2 f;
        f = __half22float2(*(const half2*)&v0.x); acc[0] += f.x; acc[1] += f.y;
        f = __half22float2(*(const half2*)&v0.y); acc[2] += f.x; acc[3] += f.y;
        f = __half22float2(*(const half2*)&v0.z); acc[4] += f.x; acc[5] += f.y;
        f = __half22float2(*(const half2*)&v0.w); acc[6] += f.x; acc[7] += f.y;
        f = __half22float2(*(const half2*)&v1.x); acc[0] += f.x; acc[1] += f.y;
        f = __half22float2(*(const half2*)&v1.y); acc[2] += f.x; acc[3] += f.y;
        f = __half22float2(*(const half2*)&v1.z); acc[4] += f.x; acc[5] += f.y;
        f = __half22float2(*(const half2*)&v1.w); acc[6] += f.x; acc[7] += f.y;
    }
    if (j < e) {
        uint32_t p0 = perm[j];
        const uint4* s0 = (const uint4*)(xt +
            (((size_t)(p0 >> 16)) * NN + (size_t)(p0 & 0xFFFFu)) * DO) + lane;
        uint4 v0 = __ldg(s0);
        float2 f;
        f = __half22float2(*(const half2*)&v0.x); acc[0] += f.x; acc[1] += f.y;
        f = __half22float2(*(const half2*)&v0.y); acc[2] += f.x; acc[3] += f.y;
        f = __half22float2(*(const half2*)&v0.z); acc[4] += f.x; acc[5] += f.y;
        f = __half22float2(*(const half2*)&v0.w); acc[6] += f.x; acc[7] += f.y;
    }

    const float4 b0 = *(const float4*)(bias + lane * 8);
    const float4 b1 = *(const float4*)(bias + lane * 8 + 4);
    float4 o0, o1;
    o0.x = fmaxf(acc[0] + b0.x, 0.f); o0.y = fmaxf(acc[1] + b0.y, 0.f);
    o0.z = fmaxf(acc[2] + b0.z, 0.f); o0.w = fmaxf(acc[3] + b0.w, 0.f);
    o1.x = fmaxf(acc[4] + b1.x, 0.f); o1.y = fmaxf(acc[5] + b1.y, 0.f);
    o1.z = fmaxf(acc[6] + b1.z, 0.f); o1.w = fmaxf(acc[7] + b1.w, 0.f);

    float* dst = out + (size_t)n * DO + lane * 8;
    *(float4*)dst = o0;
    *(float4*)(dst + 4) = o1;
}

extern "C" void kernel_launch(void* const* d_in, const int* in_sizes, int n_in,
                              void* d_out, int out_size) {
    const float* x          = (const float*)d_in[0];
    const int*   edge_index = (const int*)d_in[1];
    const int*   edge_type  = (const int*)d_in[2];
    const float* weight     = (const float*)d_in[3];
    const float* bias       = (const float*)d_in[4];
    float* out = (float*)d_out;

    float *xr, *wr;
    __half* xt;
    int *cnt, *offs, *curs;
    uint32_t* perm;
    cudaGetSymbolAddress((void**)&xr, g_xr);
    cudaGetSymbolAddress((void**)&wr, g_wr);
    cudaGetSymbolAddress((void**)&xt, g_xt);
    cudaGetSymbolAddress((void**)&cnt, g_cnt);
    cudaGetSymbolAddress((void**)&offs, g_offs);
    cudaGetSymbolAddress((void**)&curs, g_curs);
    cudaGetSymbolAddress((void**)&perm, g_perm);

    cudaFuncSetAttribute(rgcn_gemm, cudaFuncAttributeMaxDynamicSharedMemorySize, SMEM_DYN);

    const int xn4 = NN * DI / 4;
    const int wn4 = NR * DI * DO / 4;
    rgcn_round<<<(xn4 + 255) / 256, 256>>>((const float4*)x, (float4*)xr, xn4);
    rgcn_round<<<(wn4 + 255) / 256, 256>>>((const float4*)weight, (float4*)wr, wn4);

    // CSR build
    rgcn_zero_cnt<<<(NN + 255) / 256, 256>>>(cnt);
    rgcn_count<<<(NE + 255) / 256, 256>>>(edge_index, cnt);
    rgcn_scan<<<1, 1024>>>(cnt, offs, curs);
    rgcn_fill<<<(NE + 255) / 256, 256>>>(edge_index, edge_type, curs, perm);

    dim3 gg((NN + 127) / 128, DO / 128, NR);     // 391 x 2 x 8
    rgcn_gemm<<<gg, 128, SMEM_DYN>>>(xr, wr, xt);

    rgcn_aggregate<<<(NN + 7) / 8, 256>>>(xt, bias, offs, perm, out);
}